// round 2
// baseline (speedup 1.0000x reference)
#include <cuda_runtime.h>
#include <math.h>
#include <math_constants.h>

// ---------------- problem constants ----------------
#define QLEN   2500     // 50*50 query positions
#define NKLEN  6336     // 6*24*44 key positions
#define DMODEL 128
#define NHEADS 4
#define DHEAD  32
#define KTILE  32
#define SPLITS 6
#define TILES_PER_SPLIT 33   // 198 k-tiles / 6 splits
#define ATTN_SCALE 0.17677669529663688f  // 32^-0.5
#define NEG_BIG (-3.402823466e38f)       // float32 finfo.min (reference uses this, NOT -inf)

// ---------------- scratch (device globals; no allocation allowed) ----------------
__device__ float g_qf[QLEN * DMODEL];
__device__ float g_kf[NKLEN * DMODEL];
__device__ float g_vf[NKLEN * DMODEL];
__device__ float g_pm[SPLITS * NHEADS * QLEN];
__device__ float g_ps[SPLITS * NHEADS * QLEN];
__device__ float g_pacc[SPLITS * NHEADS * QLEN * DHEAD];
__device__ float g_attn[QLEN * DMODEL];
__device__ float g_z[QLEN * DMODEL];
__device__ float g_zln[QLEN * DMODEL];
__device__ float g_h1[QLEN * 2 * DMODEL];

// ---------------- packed f32x2 helpers (Blackwell FFMA2 path) ----------------
typedef unsigned long long ull;
__device__ __forceinline__ ull pack2(float x, float y) {
    ull r; asm("mov.b64 %0, {%1,%2};" : "=l"(r) : "f"(x), "f"(y)); return r;
}
__device__ __forceinline__ void unpack2(ull v, float& x, float& y) {
    asm("mov.b64 {%0,%1}, %2;" : "=f"(x), "=f"(y) : "l"(v));
}
__device__ __forceinline__ ull ffma2(ull a, ull b, ull c) {
    ull d; asm("fma.rn.f32x2 %0, %1, %2, %3;" : "=l"(d) : "l"(a), "l"(b), "l"(c)); return d;
}
__device__ __forceinline__ ull fmul2(ull a, ull b) {
    ull d; asm("mul.rn.f32x2 %0, %1, %2;" : "=l"(d) : "l"(a), "l"(b)); return d;
}
__device__ __forceinline__ ull fadd2(ull a, ull b) {
    ull d; asm("add.rn.f32x2 %0, %1, %2;" : "=l"(d) : "l"(a), "l"(b)); return d;
}

// ============================================================================
// Kernel 1: LayerNorm (over channel dim, strided input layout) + 128x128 GEMM
// input layout: x[(n*128 + d)*inner_pos + p], pos = n*inner_pos + p
// out[pos*128 + i] = LN(x[pos,:]) @ w[i,:] + bias[i]
// ============================================================================
__global__ void __launch_bounds__(256)
ln_gemm_qkv(const float* __restrict__ x, int npos, int inner_pos,
            const float* __restrict__ gam, const float* __restrict__ bet,
            const float* __restrict__ w, const float* __restrict__ bw,
            float* __restrict__ out)
{
    __shared__ float xs[32][132];
    __shared__ float mu[32], rs[32];
    const int tid = threadIdx.x;
    const int pos0 = blockIdx.x * 32;

    // load + transpose tile: coalesced over contiguous p
    #pragma unroll
    for (int it = 0; it < 16; it++) {
        int idx = tid + it * 256;
        int d = idx >> 5, j = idx & 31;
        int pos = pos0 + j;
        float v = 0.f;
        if (pos < npos) {
            int n = pos / inner_pos;
            int p = pos - n * inner_pos;
            v = x[((size_t)n * DMODEL + d) * (size_t)inner_pos + p];
        }
        xs[j][d] = v;
    }
    __syncthreads();

    if (tid < 32) {
        float m = 0.f;
        #pragma unroll 8
        for (int d = 0; d < 128; d++) m += xs[tid][d];
        m *= (1.f / 128.f);
        float v = 0.f;
        #pragma unroll 8
        for (int d = 0; d < 128; d++) { float t = xs[tid][d] - m; v += t * t; }
        v *= (1.f / 128.f);
        mu[tid] = m;
        rs[tid] = rsqrtf(v + 1e-5f);
    }
    __syncthreads();

    #pragma unroll
    for (int it = 0; it < 16; it++) {
        int idx = tid + it * 256;
        int j = idx >> 7, d = idx & 127;
        xs[j][d] = (xs[j][d] - mu[j]) * rs[j] * gam[d] + bet[d];
    }
    __syncthreads();

    // GEMM: each thread does 4 rows x 4 cols
    float acc[4][4];
    #pragma unroll
    for (int r = 0; r < 4; r++)
        #pragma unroll
        for (int c = 0; c < 4; c++) acc[r][c] = 0.f;

    const int j0 = (tid >> 5) * 4;
    const int i0 = (tid & 31) * 4;
    for (int d = 0; d < 128; d += 4) {
        float4 xv[4];
        #pragma unroll
        for (int r = 0; r < 4; r++) xv[r] = *(const float4*)&xs[j0 + r][d];
        #pragma unroll
        for (int c = 0; c < 4; c++) {
            float4 wv = __ldg((const float4*)&w[(size_t)(i0 + c) * 128 + d]);
            #pragma unroll
            for (int r = 0; r < 4; r++)
                acc[r][c] += xv[r].x * wv.x + xv[r].y * wv.y + xv[r].z * wv.z + xv[r].w * wv.w;
        }
    }
    #pragma unroll
    for (int r = 0; r < 4; r++) {
        int pos = pos0 + j0 + r;
        if (pos < npos) {
            #pragma unroll
            for (int c = 0; c < 4; c++)
                out[(size_t)pos * 128 + i0 + c] = acc[r][c] + bw[i0 + c];
        }
    }
}

// ============================================================================
// Kernel 2: split-K flash attention, online softmax, f32x2 packed FMAs.
// grid: (ceil(Q/32), SPLITS), block 128 = 4 warps (warp h = head h, lane = q)
// ============================================================================
__global__ void __launch_bounds__(128)
attn_kernel(const float* __restrict__ Wl, const int* __restrict__ vis)
{
    __shared__ float Ks[KTILE][128];
    __shared__ float Vs[KTILE][128];
    __shared__ float Ws[32][KTILE + 1];
    __shared__ int   Bs[32][KTILE + 1];

    const int tid = threadIdx.x;
    const int lane = tid & 31;
    const int h = tid >> 5;
    const int qb = blockIdx.x;
    const int split = blockIdx.y;
    const int row = qb * 32 + lane;
    const bool valid = row < QLEN;

    ull q2[16];
    if (valid) {
        const float4* qp = (const float4*)&g_qf[(size_t)row * 128 + h * 32];
        #pragma unroll
        for (int t = 0; t < 8; t++) {
            float4 v = qp[t];
            q2[2 * t]     = pack2(v.x, v.y);
            q2[2 * t + 1] = pack2(v.z, v.w);
        }
    }
    ull acc2[16];
    #pragma unroll
    for (int t = 0; t < 16; t++) acc2[t] = 0ull;
    float m = -CUDART_INF_F, s = 0.f;

    const int t0 = split * TILES_PER_SPLIT;
    for (int tile = t0; tile < t0 + TILES_PER_SPLIT; ++tile) {
        const int k0 = tile * KTILE;
        const float4* ksrc = (const float4*)&g_kf[(size_t)k0 * 128];
        const float4* vsrc = (const float4*)&g_vf[(size_t)k0 * 128];
        float4* kd = (float4*)Ks;
        float4* vd = (float4*)Vs;
        #pragma unroll
        for (int it = 0; it < 8; it++) {
            int idx = tid + it * 128;
            kd[idx] = ksrc[idx];
            vd[idx] = vsrc[idx];
        }
        #pragma unroll
        for (int it = 0; it < 8; it++) {
            int idx = tid + it * 128;
            int j = idx >> 5, kk = idx & 31;
            int r = qb * 32 + j;
            float wv = 0.f; int bv = 0;
            if (r < QLEN) {
                size_t off = (size_t)r * NKLEN + k0 + kk;
                wv = Wl[off];
                bv = vis[off];
            }
            Ws[j][kk] = wv;
            Bs[j][kk] = bv;
        }
        __syncthreads();

        if (valid) {
            #pragma unroll 4
            for (int kk = 0; kk < KTILE; ++kk) {
                const ull* kp = (const ull*)&Ks[kk][h * 32];
                ull d0 = 0, d1 = 0, d2 = 0, d3 = 0;
                #pragma unroll
                for (int t = 0; t < 4; t++) {
                    d0 = ffma2(q2[4 * t + 0], kp[4 * t + 0], d0);
                    d1 = ffma2(q2[4 * t + 1], kp[4 * t + 1], d1);
                    d2 = ffma2(q2[4 * t + 2], kp[4 * t + 2], d2);
                    d3 = ffma2(q2[4 * t + 3], kp[4 * t + 3], d3);
                }
                d0 = fadd2(d0, d1);
                d2 = fadd2(d2, d3);
                d0 = fadd2(d0, d2);
                float a, b; unpack2(d0, a, b);
                float dot = a + b;

                float wv = Ws[lane][kk];
                // reference: logits = where(vis==0, finfo.min, qk*scale) * W
                float l = (Bs[lane][kk] == 0 ? NEG_BIG : dot * ATTN_SCALE) * wv;
                float mn = fmaxf(m, l);
                if (mn > m) {
                    float corr = __expf(m - mn);   // first iter: expf(-inf)=0, state was 0
                    s *= corr;
                    ull c2 = pack2(corr, corr);
                    #pragma unroll
                    for (int t = 0; t < 16; t++) acc2[t] = fmul2(acc2[t], c2);
                    m = mn;
                }
                float p = __expf(l - m);
                s += p;
                ull p2 = pack2(p, p);
                const ull* vp = (const ull*)&Vs[kk][h * 32];
                #pragma unroll
                for (int t = 0; t < 16; t++) acc2[t] = ffma2(p2, vp[t], acc2[t]);
            }
        }
        __syncthreads();
    }

    if (valid) {
        int pidx = (split * NHEADS + h) * QLEN + row;
        g_pm[pidx] = m;
        g_ps[pidx] = s;
        ull* pa = (ull*)&g_pacc[(size_t)pidx * DHEAD];
        #pragma unroll
        for (int t = 0; t < 16; t++) pa[t] = acc2[t];
    }
}

// ============================================================================
// Kernel 3: combine split-K partials -> g_attn[q][h*32+d]
// ============================================================================
__global__ void __launch_bounds__(128)
combine_kernel()
{
    int idx = blockIdx.x * blockDim.x + threadIdx.x;
    if (idx >= NHEADS * QLEN) return;
    int h = idx / QLEN;
    int row = idx - h * QLEN;

    float M = -CUDART_INF_F;
    #pragma unroll
    for (int s = 0; s < SPLITS; s++)
        M = fmaxf(M, g_pm[(s * NHEADS + h) * QLEN + row]);

    float S = 0.f;
    float acc[DHEAD];
    #pragma unroll
    for (int d = 0; d < DHEAD; d++) acc[d] = 0.f;

    #pragma unroll
    for (int s = 0; s < SPLITS; s++) {
        int p = (s * NHEADS + h) * QLEN + row;
        float e = __expf(g_pm[p] - M);
        S += g_ps[p] * e;
        const float* pa = &g_pacc[(size_t)p * DHEAD];
        #pragma unroll
        for (int d = 0; d < DHEAD; d++) acc[d] += pa[d] * e;
    }
    float inv = 1.f / S;
    float* o = &g_attn[(size_t)row * 128 + h * 32];
    #pragma unroll
    for (int d = 0; d < DHEAD; d++) o[d] = acc[d] * inv;
}

// ============================================================================
// Kernel 4: output projection + skip (skip layout is [D][Q])
// ============================================================================
__global__ void __launch_bounds__(256)
proj_skip(const float* __restrict__ w, const float* __restrict__ bw,
          const float* __restrict__ skip)
{
    __shared__ float xs[32][132];
    const int tid = threadIdx.x;
    const int pos0 = blockIdx.x * 32;

    #pragma unroll
    for (int it = 0; it < 16; it++) {
        int idx = tid + it * 256;
        int j = idx >> 7, d = idx & 127;
        int pos = pos0 + j;
        xs[j][d] = (pos < QLEN) ? g_attn[(size_t)pos * 128 + d] : 0.f;
    }
    __syncthreads();

    float acc[4][4];
    #pragma unroll
    for (int r = 0; r < 4; r++)
        #pragma unroll
        for (int c = 0; c < 4; c++) acc[r][c] = 0.f;

    const int j0 = (tid >> 5) * 4;
    const int i0 = (tid & 31) * 4;
    for (int d = 0; d < 128; d += 4) {
        float4 xv[4];
        #pragma unroll
        for (int r = 0; r < 4; r++) xv[r] = *(const float4*)&xs[j0 + r][d];
        #pragma unroll
        for (int c = 0; c < 4; c++) {
            float4 wv = __ldg((const float4*)&w[(size_t)(i0 + c) * 128 + d]);
            #pragma unroll
            for (int r = 0; r < 4; r++)
                acc[r][c] += xv[r].x * wv.x + xv[r].y * wv.y + xv[r].z * wv.z + xv[r].w * wv.w;
        }
    }
    #pragma unroll
    for (int r = 0; r < 4; r++) {
        int pos = pos0 + j0 + r;
        if (pos < QLEN) {
            #pragma unroll
            for (int c = 0; c < 4; c++)
                g_z[(size_t)pos * 128 + i0 + c] =
                    acc[r][c] + bw[i0 + c] + skip[(size_t)(i0 + c) * QLEN + pos];
        }
    }
}

// ============================================================================
// Kernel 5: pre-LN -> store zln; fc1 (128->256) + exact GELU -> g_h1
// ============================================================================
__global__ void __launch_bounds__(256)
mlp1(const float* __restrict__ gam, const float* __restrict__ bet,
     const float* __restrict__ w1, const float* __restrict__ b1)
{
    __shared__ float xs[32][132];
    __shared__ float mu[32], rs[32];
    const int tid = threadIdx.x;
    const int pos0 = blockIdx.x * 32;

    #pragma unroll
    for (int it = 0; it < 16; it++) {
        int idx = tid + it * 256;
        int j = idx >> 7, d = idx & 127;
        int pos = pos0 + j;
        xs[j][d] = (pos < QLEN) ? g_z[(size_t)pos * 128 + d] : 0.f;
    }
    __syncthreads();

    if (tid < 32) {
        float m = 0.f;
        #pragma unroll 8
        for (int d = 0; d < 128; d++) m += xs[tid][d];
        m *= (1.f / 128.f);
        float v = 0.f;
        #pragma unroll 8
        for (int d = 0; d < 128; d++) { float t = xs[tid][d] - m; v += t * t; }
        v *= (1.f / 128.f);
        mu[tid] = m;
        rs[tid] = rsqrtf(v + 1e-5f);
    }
    __syncthreads();

    #pragma unroll
    for (int it = 0; it < 16; it++) {
        int idx = tid + it * 256;
        int j = idx >> 7, d = idx & 127;
        float v = (xs[j][d] - mu[j]) * rs[j] * gam[d] + bet[d];
        xs[j][d] = v;
        int pos = pos0 + j;
        if (pos < QLEN) g_zln[(size_t)pos * 128 + d] = v;
    }
    __syncthreads();

    // GEMM 32 x 256: each thread 4 rows x 8 cols
    float acc[4][8];
    #pragma unroll
    for (int r = 0; r < 4; r++)
        #pragma unroll
        for (int c = 0; c < 8; c++) acc[r][c] = 0.f;

    const int j0 = (tid >> 5) * 4;
    const int i0 = (tid & 31) * 8;
    for (int d = 0; d < 128; d += 4) {
        float4 xv[4];
        #pragma unroll
        for (int r = 0; r < 4; r++) xv[r] = *(const float4*)&xs[j0 + r][d];
        #pragma unroll
        for (int c = 0; c < 8; c++) {
            float4 wv = __ldg((const float4*)&w1[(size_t)(i0 + c) * 128 + d]);
            #pragma unroll
            for (int r = 0; r < 4; r++)
                acc[r][c] += xv[r].x * wv.x + xv[r].y * wv.y + xv[r].z * wv.z + xv[r].w * wv.w;
        }
    }
    #pragma unroll
    for (int r = 0; r < 4; r++) {
        int pos = pos0 + j0 + r;
        if (pos < QLEN) {
            #pragma unroll
            for (int c = 0; c < 8; c++) {
                float u = acc[r][c] + b1[i0 + c];
                // exact GELU: 0.5*x*(1+erf(x/sqrt(2)))
                g_h1[(size_t)pos * 256 + i0 + c] =
                    0.5f * u * (1.f + erff(u * 0.70710678118654752f));
            }
        }
    }
}

// ============================================================================
// Kernel 6: fc2 (256->128) + residual zln + post-LN + transposed output [D][Q]
// ============================================================================
__global__ void __launch_bounds__(256)
mlp2(const float* __restrict__ w2, const float* __restrict__ b2,
     const float* __restrict__ gam, const float* __restrict__ bet,
     float* __restrict__ out)
{
    __shared__ float sbuf[32 * 264];   // reused: first [32][264] h1-tile, then [32][132] y-tile
    __shared__ float mu[32], rs[32];
    const int tid = threadIdx.x;
    const int pos0 = blockIdx.x * 32;

    #pragma unroll
    for (int it = 0; it < 32; it++) {
        int idx = tid + it * 256;
        int j = idx >> 8, d = idx & 255;
        int pos = pos0 + j;
        sbuf[j * 264 + d] = (pos < QLEN) ? g_h1[(size_t)pos * 256 + d] : 0.f;
    }
    __syncthreads();

    float acc[4][4];
    #pragma unroll
    for (int r = 0; r < 4; r++)
        #pragma unroll
        for (int c = 0; c < 4; c++) acc[r][c] = 0.f;

    const int j0 = (tid >> 5) * 4;
    const int i0 = (tid & 31) * 4;
    for (int d = 0; d < 256; d += 4) {
        float4 xv[4];
        #pragma unroll
        for (int r = 0; r < 4; r++) xv[r] = *(const float4*)&sbuf[(j0 + r) * 264 + d];
        #pragma unroll
        for (int c = 0; c < 4; c++) {
            float4 wv = __ldg((const float4*)&w2[(size_t)(i0 + c) * 256 + d]);
            #pragma unroll
            for (int r = 0; r < 4; r++)
                acc[r][c] += xv[r].x * wv.x + xv[r].y * wv.y + xv[r].z * wv.z + xv[r].w * wv.w;
        }
    }
    __syncthreads();   // done reading h1 tile; sbuf now reused as y tile [32][132]

    #pragma unroll
    for (int r = 0; r < 4; r++) {
        int pos = pos0 + j0 + r;
        #pragma unroll
        for (int c = 0; c < 4; c++) {
            float zl = (pos < QLEN) ? g_zln[(size_t)pos * 128 + i0 + c] : 0.f;
            sbuf[(j0 + r) * 132 + i0 + c] = acc[r][c] + b2[i0 + c] + zl;
        }
    }
    __syncthreads();

    if (tid < 32) {
        float m = 0.f;
        #pragma unroll 8
        for (int d = 0; d < 128; d++) m += sbuf[tid * 132 + d];
        m *= (1.f / 128.f);
        float v = 0.f;
        #pragma unroll 8
        for (int d = 0; d < 128; d++) { float t = sbuf[tid * 132 + d] - m; v += t * t; }
        v *= (1.f / 128.f);
        mu[tid] = m;
        rs[tid] = rsqrtf(v + 1e-5f);
    }
    __syncthreads();

    #pragma unroll
    for (int it = 0; it < 16; it++) {
        int idx = tid + it * 256;
        int d = idx >> 5, j = idx & 31;
        int pos = pos0 + j;
        if (pos < QLEN)
            out[(size_t)d * QLEN + pos] =
                (sbuf[j * 132 + d] - mu[j]) * rs[j] * gam[d] + bet[d];
    }
}

// ============================================================================
// launch
// ============================================================================
extern "C" void kernel_launch(void* const* d_in, const int* in_sizes, int n_in,
                              void* d_out, int out_size)
{
    const float* q      = (const float*)d_in[0];
    const float* k      = (const float*)d_in[1];
    const float* v      = (const float*)d_in[2];
    const float* Wl     = (const float*)d_in[3];
    const int*   vis    = (const int*)  d_in[4];
    const float* skip   = (const float*)d_in[5];
    const float* qn_g   = (const float*)d_in[6];
    const float* qn_b   = (const float*)d_in[7];
    const float* kn_g   = (const float*)d_in[8];
    const float* kn_b   = (const float*)d_in[9];
    const float* vn_g   = (const float*)d_in[10];
    const float* vn_b   = (const float*)d_in[11];
    const float* wq     = (const float*)d_in[12];
    const float* bq     = (const float*)d_in[13];
    const float* wk     = (const float*)d_in[14];
    const float* bk     = (const float*)d_in[15];
    const float* wv     = (const float*)d_in[16];
    const float* bv     = (const float*)d_in[17];
    const float* wproj  = (const float*)d_in[18];
    const float* bproj  = (const float*)d_in[19];
    const float* pre_g  = (const float*)d_in[20];
    const float* pre_b  = (const float*)d_in[21];
    const float* w1     = (const float*)d_in[22];
    const float* b1     = (const float*)d_in[23];
    const float* w2     = (const float*)d_in[24];
    const float* b2     = (const float*)d_in[25];
    const float* post_g = (const float*)d_in[26];
    const float* post_b = (const float*)d_in[27];
    float* out = (float*)d_out;

    float *qf_p, *kf_p, *vf_p;
    cudaGetSymbolAddress((void**)&qf_p, g_qf);
    cudaGetSymbolAddress((void**)&kf_p, g_kf);
    cudaGetSymbolAddress((void**)&vf_p, g_vf);

    const int QB = (QLEN + 31) / 32;    // 79
    const int KB = (NKLEN + 31) / 32;   // 198

    ln_gemm_qkv<<<QB, 256>>>(q, QLEN, QLEN, qn_g, qn_b, wq, bq, qf_p);
    ln_gemm_qkv<<<KB, 256>>>(k, NKLEN, 1056, kn_g, kn_b, wk, bk, kf_p);
    ln_gemm_qkv<<<KB, 256>>>(v, NKLEN, 1056, vn_g, vn_b, wv, bv, vf_p);

    dim3 ag(QB, SPLITS);
    attn_kernel<<<ag, 128>>>(Wl, vis);

    combine_kernel<<<(NHEADS * QLEN + 127) / 128, 128>>>();

    proj_skip<<<QB, 256>>>(wproj, bproj, skip);
    mlp1<<<QB, 256>>>(pre_g, pre_b, w1, b1);
    mlp2<<<QB, 256>>>(w2, b2, post_g, post_b, out);
}

// round 4
// speedup vs baseline: 1.8883x; 1.8883x over previous
#include <cuda_runtime.h>
#include <cuda_bf16.h>
#include <cstdint>
#include <math.h>
#include <math_constants.h>

typedef unsigned int       u32;
typedef unsigned long long u64;

// ---------------- problem constants ----------------
#define QLEN   2500
#define NKLEN  6336
#define DMODEL 128
#define NHEADS 4
#define DHEAD  32
#define SPLITS 4
#define NKT    198          // 6336/32 key tiles
#define TPS    50           // tiles per split (last split gets 48)
#define ATTN_SCALE 0.17677669529663688f
#define NEG_BIG (-3.402823466e38f)   // float32 finfo.min (reference semantics)

// ---------------- scratch ----------------
__device__ __nv_bfloat16 g_qbf[NHEADS * QLEN * DHEAD];
__device__ __nv_bfloat16 g_kbf[NHEADS * NKLEN * DHEAD];
__device__ __nv_bfloat16 g_vbf[NHEADS * NKLEN * DHEAD];
__device__ float g_pm[SPLITS * NHEADS * QLEN];
__device__ float g_ps[SPLITS * NHEADS * QLEN];
__device__ float g_pacc[SPLITS * NHEADS * QLEN * DHEAD];
__device__ float g_attn[QLEN * DMODEL];
__device__ float g_z[QLEN * DMODEL];
__device__ float g_zln[QLEN * DMODEL];
__device__ float g_h1[QLEN * 2 * DMODEL];

// ---------------- helpers ----------------
__device__ __forceinline__ u32 packbf(float lo, float hi) {
    u32 r;
    asm("cvt.rn.bf16x2.f32 %0, %1, %2;" : "=r"(r) : "f"(hi), "f"(lo));
    return r;
}

__device__ __forceinline__ void mma16816(float (&c)[4],
                                         u32 a0, u32 a1, u32 a2, u32 a3,
                                         u32 b0, u32 b1) {
    asm volatile(
        "mma.sync.aligned.m16n8k16.row.col.f32.bf16.bf16.f32 "
        "{%0,%1,%2,%3}, {%4,%5,%6,%7}, {%8,%9}, {%0,%1,%2,%3};"
        : "+f"(c[0]), "+f"(c[1]), "+f"(c[2]), "+f"(c[3])
        : "r"(a0), "r"(a1), "r"(a2), "r"(a3), "r"(b0), "r"(b1));
}

// ============================================================================
// Kernel 1: LayerNorm + 128x128 GEMM -> bf16 planar [h][pos][32]
// input layout: x[(n*128 + d)*inner_pos + p], pos = n*inner_pos + p
// ============================================================================
__global__ void __launch_bounds__(256)
ln_gemm_qkv(const float* __restrict__ x, int npos, int inner_pos,
            const float* __restrict__ gam, const float* __restrict__ bet,
            const float* __restrict__ w, const float* __restrict__ bw,
            __nv_bfloat16* __restrict__ outb)
{
    __shared__ float xs[32][132];
    __shared__ float mu[32], rs[32];
    const int tid = threadIdx.x;
    const int pos0 = blockIdx.x * 32;

    #pragma unroll
    for (int it = 0; it < 16; it++) {
        int idx = tid + it * 256;
        int d = idx >> 5, j = idx & 31;
        int pos = pos0 + j;
        float v = 0.f;
        if (pos < npos) {
            int n = pos / inner_pos;
            int p = pos - n * inner_pos;
            v = x[((size_t)n * DMODEL + d) * (size_t)inner_pos + p];
        }
        xs[j][d] = v;
    }
    __syncthreads();

    // parallel LN stats: 8 lanes per row
    {
        const int j = tid >> 3, ls = tid & 7;
        float mm = 0.f;
        #pragma unroll
        for (int d = ls; d < 128; d += 8) mm += xs[j][d];
        mm += __shfl_xor_sync(0xffffffffu, mm, 1);
        mm += __shfl_xor_sync(0xffffffffu, mm, 2);
        mm += __shfl_xor_sync(0xffffffffu, mm, 4);
        mm *= (1.f / 128.f);
        float vv = 0.f;
        #pragma unroll
        for (int d = ls; d < 128; d += 8) { float t = xs[j][d] - mm; vv += t * t; }
        vv += __shfl_xor_sync(0xffffffffu, vv, 1);
        vv += __shfl_xor_sync(0xffffffffu, vv, 2);
        vv += __shfl_xor_sync(0xffffffffu, vv, 4);
        vv *= (1.f / 128.f);
        if (ls == 0) { mu[j] = mm; rs[j] = rsqrtf(vv + 1e-5f); }
    }
    __syncthreads();

    #pragma unroll
    for (int it = 0; it < 16; it++) {
        int idx = tid + it * 256;
        int j = idx >> 7, d = idx & 127;
        xs[j][d] = (xs[j][d] - mu[j]) * rs[j] * gam[d] + bet[d];
    }
    __syncthreads();

    float acc[4][4];
    #pragma unroll
    for (int r = 0; r < 4; r++)
        #pragma unroll
        for (int c = 0; c < 4; c++) acc[r][c] = 0.f;

    const int j0 = (tid >> 5) * 4;
    const int i0 = (tid & 31) * 4;
    for (int d = 0; d < 128; d += 4) {
        float4 xv[4];
        #pragma unroll
        for (int r = 0; r < 4; r++) xv[r] = *(const float4*)&xs[j0 + r][d];
        #pragma unroll
        for (int c = 0; c < 4; c++) {
            float4 wv = __ldg((const float4*)&w[(size_t)(i0 + c) * 128 + d]);
            #pragma unroll
            for (int r = 0; r < 4; r++)
                acc[r][c] += xv[r].x * wv.x + xv[r].y * wv.y + xv[r].z * wv.z + xv[r].w * wv.w;
        }
    }
    const int h = i0 >> 5;
    const int dbase = i0 & 31;
    #pragma unroll
    for (int r = 0; r < 4; r++) {
        int pos = pos0 + j0 + r;
        if (pos < npos) {
            uint2 u;
            u.x = packbf(acc[r][0] + bw[i0 + 0], acc[r][1] + bw[i0 + 1]);
            u.y = packbf(acc[r][2] + bw[i0 + 2], acc[r][3] + bw[i0 + 3]);
            *(uint2*)&outb[((size_t)h * npos + pos) * DHEAD + dbase] = u;
        }
    }
}

// ============================================================================
// Kernel 2: HMMA bf16 flash attention with split-K.
// grid (79 qtiles, SPLITS). block 256 = 8 warps: warp = (head = w&3, rowgrp = w>>2).
// Each block: 32 q rows, all 4 heads, shared smem W/vis tile.
// ============================================================================
__global__ void __launch_bounds__(256, 2)
attn_kernel(const float* __restrict__ Wl, const int* __restrict__ vis)
{
    __shared__ __nv_bfloat16 Ks[NHEADS][32][36];
    __shared__ __nv_bfloat16 Vs[NHEADS][32][40];
    __shared__ float Ws[32][36];
    __shared__ int   Bv[32][36];

    const int tid = threadIdx.x;
    const int lane = tid & 31;
    const int wid = tid >> 5;
    const int h = wid & 3;
    const int rg = wid >> 2;
    const int g = lane >> 2;
    const int tx = lane & 3;
    const int qt = blockIdx.x;
    const int split = blockIdx.y;

    const int q0 = qt * 32 + rg * 16;
    const int r_lo = q0 + g;
    const int r_hi = q0 + g + 8;

    // Q A-frags (row-major m16 x k16, two k-chunks)
    u32 aQ[2][4];
    #pragma unroll
    for (int kc = 0; kc < 2; kc++) {
        int c0 = kc * 16 + 2 * tx;
        aQ[kc][0] = (r_lo < QLEN) ? *(const u32*)&g_qbf[((size_t)h * QLEN + r_lo) * DHEAD + c0]     : 0u;
        aQ[kc][1] = (r_hi < QLEN) ? *(const u32*)&g_qbf[((size_t)h * QLEN + r_hi) * DHEAD + c0]     : 0u;
        aQ[kc][2] = (r_lo < QLEN) ? *(const u32*)&g_qbf[((size_t)h * QLEN + r_lo) * DHEAD + c0 + 8] : 0u;
        aQ[kc][3] = (r_hi < QLEN) ? *(const u32*)&g_qbf[((size_t)h * QLEN + r_hi) * DHEAD + c0 + 8] : 0u;
    }

    float acc[4][4];
    #pragma unroll
    for (int nc = 0; nc < 4; nc++)
        #pragma unroll
        for (int i = 0; i < 4; i++) acc[nc][i] = 0.f;
    float m0 = -CUDART_INF_F, m1 = -CUDART_INF_F, s0 = 0.f, s1 = 0.f;

    const int t0 = split * TPS;
    const int t1 = (t0 + TPS < NKT) ? t0 + TPS : NKT;

    for (int kt = t0; kt < t1; kt++) {
        const int k0 = kt * 32;
        // cooperative loads: K,V (4 heads x 32 keys x 32 dh bf16)
        #pragma unroll
        for (int it = 0; it < 8; it++) {
            int u = tid + it * 256;
            int hh = u >> 9;
            int rem = u & 511;
            int key = rem >> 4;
            int dp = (rem & 15) * 2;
            size_t src = ((size_t)hh * NKLEN + k0 + key) * DHEAD + dp;
            *(u32*)&Ks[hh][key][dp] = *(const u32*)&g_kbf[src];
            *(u32*)&Vs[hh][key][dp] = *(const u32*)&g_vbf[src];
        }
        // W / vis tile (32 rows x 32 cols), shared by all heads
        {
            int row = tid >> 3, c4 = (tid & 7) * 4;
            int qq = qt * 32 + row; if (qq >= QLEN) qq = QLEN - 1;
            *(float4*)&Ws[row][c4] = __ldg((const float4*)&Wl[(size_t)qq * NKLEN + k0 + c4]);
            *(int4*)&Bv[row][c4]   = __ldg((const int4*)&vis[(size_t)qq * NKLEN + k0 + c4]);
        }
        __syncthreads();

        // S = Q K^T  (16 rows x 32 keys per warp)
        float S[4][4];
        #pragma unroll
        for (int nc = 0; nc < 4; nc++) {
            S[nc][0] = 0.f; S[nc][1] = 0.f; S[nc][2] = 0.f; S[nc][3] = 0.f;
            #pragma unroll
            for (int kc = 0; kc < 2; kc++) {
                u32 b0 = *(const u32*)&Ks[h][nc * 8 + g][kc * 16 + 2 * tx];
                u32 b1 = *(const u32*)&Ks[h][nc * 8 + g][kc * 16 + 8 + 2 * tx];
                mma16816(S[nc], aQ[kc][0], aQ[kc][1], aQ[kc][2], aQ[kc][3], b0, b1);
            }
        }

        // logits: (vis==0 ? NEG_BIG : s*scale) * W
        float l[4][4];
        const int wr_lo = rg * 16 + g;
        const int wr_hi = wr_lo + 8;
        #pragma unroll
        for (int nc = 0; nc < 4; nc++) {
            float2 wl = *(const float2*)&Ws[wr_lo][nc * 8 + 2 * tx];
            float2 wh = *(const float2*)&Ws[wr_hi][nc * 8 + 2 * tx];
            int2 bl = *(const int2*)&Bv[wr_lo][nc * 8 + 2 * tx];
            int2 bh = *(const int2*)&Bv[wr_hi][nc * 8 + 2 * tx];
            l[nc][0] = (bl.x == 0 ? NEG_BIG : S[nc][0] * ATTN_SCALE) * wl.x;
            l[nc][1] = (bl.y == 0 ? NEG_BIG : S[nc][1] * ATTN_SCALE) * wl.y;
            l[nc][2] = (bh.x == 0 ? NEG_BIG : S[nc][2] * ATTN_SCALE) * wh.x;
            l[nc][3] = (bh.y == 0 ? NEG_BIG : S[nc][3] * ATTN_SCALE) * wh.y;
        }

        // online softmax (rows g and g+8 per thread)
        float mx0 = fmaxf(fmaxf(l[0][0], l[0][1]), fmaxf(l[1][0], l[1][1]));
        mx0 = fmaxf(mx0, fmaxf(fmaxf(l[2][0], l[2][1]), fmaxf(l[3][0], l[3][1])));
        float mx1 = fmaxf(fmaxf(l[0][2], l[0][3]), fmaxf(l[1][2], l[1][3]));
        mx1 = fmaxf(mx1, fmaxf(fmaxf(l[2][2], l[2][3]), fmaxf(l[3][2], l[3][3])));
        mx0 = fmaxf(mx0, __shfl_xor_sync(0xffffffffu, mx0, 1));
        mx0 = fmaxf(mx0, __shfl_xor_sync(0xffffffffu, mx0, 2));
        mx1 = fmaxf(mx1, __shfl_xor_sync(0xffffffffu, mx1, 1));
        mx1 = fmaxf(mx1, __shfl_xor_sync(0xffffffffu, mx1, 2));
        float mn0 = fmaxf(m0, mx0);
        float mn1 = fmaxf(m1, mx1);
        float cr0 = __expf(m0 - mn0);
        float cr1 = __expf(m1 - mn1);
        m0 = mn0; m1 = mn1;
        s0 *= cr0; s1 *= cr1;
        #pragma unroll
        for (int nc = 0; nc < 4; nc++) {
            acc[nc][0] *= cr0; acc[nc][1] *= cr0;
            acc[nc][2] *= cr1; acc[nc][3] *= cr1;
        }
        float p[4][4];
        #pragma unroll
        for (int nc = 0; nc < 4; nc++) {
            p[nc][0] = __expf(l[nc][0] - m0);
            p[nc][1] = __expf(l[nc][1] - m0);
            p[nc][2] = __expf(l[nc][2] - m1);
            p[nc][3] = __expf(l[nc][3] - m1);
            s0 += p[nc][0] + p[nc][1];
            s1 += p[nc][2] + p[nc][3];
        }

        // PV: acc += P(16x32) * V(32keys x 32dh)
        #pragma unroll
        for (int kc = 0; kc < 2; kc++) {
            u32 a0 = packbf(p[2 * kc][0],     p[2 * kc][1]);
            u32 a1 = packbf(p[2 * kc][2],     p[2 * kc][3]);
            u32 a2 = packbf(p[2 * kc + 1][0], p[2 * kc + 1][1]);
            u32 a3 = packbf(p[2 * kc + 1][2], p[2 * kc + 1][3]);
            int keyrow = kc * 16 + (lane & 15);
            #pragma unroll
            for (int nc = 0; nc < 4; nc++) {
                u32 addr = (u32)__cvta_generic_to_shared(&Vs[h][keyrow][nc * 8]);
                u32 b0, b1;
                asm volatile("ldmatrix.sync.aligned.m8n8.x2.trans.shared.b16 {%0,%1}, [%2];"
                             : "=r"(b0), "=r"(b1) : "r"(addr));
                mma16816(acc[nc], a0, a1, a2, a3, b0, b1);
            }
        }
        __syncthreads();
    }

    // epilogue: quad-reduce s, store partials
    s0 += __shfl_xor_sync(0xffffffffu, s0, 1);
    s0 += __shfl_xor_sync(0xffffffffu, s0, 2);
    s1 += __shfl_xor_sync(0xffffffffu, s1, 1);
    s1 += __shfl_xor_sync(0xffffffffu, s1, 2);

    const int base = (split * NHEADS + h) * QLEN;
    if (tx == 0) {
        if (r_lo < QLEN) { g_pm[base + r_lo] = m0; g_ps[base + r_lo] = s0; }
        if (r_hi < QLEN) { g_pm[base + r_hi] = m1; g_ps[base + r_hi] = s1; }
    }
    #pragma unroll
    for (int nc = 0; nc < 4; nc++) {
        if (r_lo < QLEN)
            *(float2*)&g_pacc[((size_t)(base + r_lo)) * DHEAD + nc * 8 + 2 * tx] =
                make_float2(acc[nc][0], acc[nc][1]);
        if (r_hi < QLEN)
            *(float2*)&g_pacc[((size_t)(base + r_hi)) * DHEAD + nc * 8 + 2 * tx] =
                make_float2(acc[nc][2], acc[nc][3]);
    }
}

// ============================================================================
// Kernel 3: combine split-K partials -> g_attn[q][h*32+d]
// ============================================================================
__global__ void __launch_bounds__(128)
combine_kernel()
{
    int idx = blockIdx.x * blockDim.x + threadIdx.x;
    if (idx >= NHEADS * QLEN) return;
    int h = idx / QLEN;
    int row = idx - h * QLEN;

    float M = -CUDART_INF_F;
    #pragma unroll
    for (int s = 0; s < SPLITS; s++)
        M = fmaxf(M, g_pm[(s * NHEADS + h) * QLEN + row]);

    float S = 0.f;
    float acc[DHEAD];
    #pragma unroll
    for (int d = 0; d < DHEAD; d++) acc[d] = 0.f;

    #pragma unroll
    for (int s = 0; s < SPLITS; s++) {
        int p = (s * NHEADS + h) * QLEN + row;
        float e = __expf(g_pm[p] - M);
        S += g_ps[p] * e;
        const float* pa = &g_pacc[(size_t)p * DHEAD];
        #pragma unroll
        for (int d = 0; d < DHEAD; d++) acc[d] += pa[d] * e;
    }
    float inv = 1.f / S;
    float* o = &g_attn[(size_t)row * DMODEL + h * DHEAD];
    #pragma unroll
    for (int d = 0; d < DHEAD; d++) o[d] = acc[d] * inv;
}

// ============================================================================
// Kernel 4: output projection + skip (skip layout [D][Q])
// ============================================================================
__global__ void __launch_bounds__(256)
proj_skip(const float* __restrict__ w, const float* __restrict__ bw,
          const float* __restrict__ skip)
{
    __shared__ float xs[32][132];
    const int tid = threadIdx.x;
    const int pos0 = blockIdx.x * 32;

    #pragma unroll
    for (int it = 0; it < 16; it++) {
        int idx = tid + it * 256;
        int j = idx >> 7, d = idx & 127;
        int pos = pos0 + j;
        xs[j][d] = (pos < QLEN) ? g_attn[(size_t)pos * 128 + d] : 0.f;
    }
    __syncthreads();

    float acc[4][4];
    #pragma unroll
    for (int r = 0; r < 4; r++)
        #pragma unroll
        for (int c = 0; c < 4; c++) acc[r][c] = 0.f;

    const int j0 = (tid >> 5) * 4;
    const int i0 = (tid & 31) * 4;
    for (int d = 0; d < 128; d += 4) {
        float4 xv[4];
        #pragma unroll
        for (int r = 0; r < 4; r++) xv[r] = *(const float4*)&xs[j0 + r][d];
        #pragma unroll
        for (int c = 0; c < 4; c++) {
            float4 wv = __ldg((const float4*)&w[(size_t)(i0 + c) * 128 + d]);
            #pragma unroll
            for (int r = 0; r < 4; r++)
                acc[r][c] += xv[r].x * wv.x + xv[r].y * wv.y + xv[r].z * wv.z + xv[r].w * wv.w;
        }
    }
    #pragma unroll
    for (int r = 0; r < 4; r++) {
        int pos = pos0 + j0 + r;
        if (pos < QLEN) {
            #pragma unroll
            for (int c = 0; c < 4; c++)
                g_z[(size_t)pos * 128 + i0 + c] =
                    acc[r][c] + bw[i0 + c] + skip[(size_t)(i0 + c) * QLEN + pos];
        }
    }
}

// ============================================================================
// Kernel 5: pre-LN -> zln; fc1 (128->256) + exact GELU -> g_h1
// ============================================================================
__global__ void __launch_bounds__(256)
mlp1(const float* __restrict__ gam, const float* __restrict__ bet,
     const float* __restrict__ w1, const float* __restrict__ b1)
{
    __shared__ float xs[32][132];
    __shared__ float mu[32], rs[32];
    const int tid = threadIdx.x;
    const int pos0 = blockIdx.x * 32;

    #pragma unroll
    for (int it = 0; it < 16; it++) {
        int idx = tid + it * 256;
        int j = idx >> 7, d = idx & 127;
        int pos = pos0 + j;
        xs[j][d] = (pos < QLEN) ? g_z[(size_t)pos * 128 + d] : 0.f;
    }
    __syncthreads();

    {
        const int j = tid >> 3, ls = tid & 7;
        float mm = 0.f;
        #pragma unroll
        for (int d = ls; d < 128; d += 8) mm += xs[j][d];
        mm += __shfl_xor_sync(0xffffffffu, mm, 1);
        mm += __shfl_xor_sync(0xffffffffu, mm, 2);
        mm += __shfl_xor_sync(0xffffffffu, mm, 4);
        mm *= (1.f / 128.f);
        float vv = 0.f;
        #pragma unroll
        for (int d = ls; d < 128; d += 8) { float t = xs[j][d] - mm; vv += t * t; }
        vv += __shfl_xor_sync(0xffffffffu, vv, 1);
        vv += __shfl_xor_sync(0xffffffffu, vv, 2);
        vv += __shfl_xor_sync(0xffffffffu, vv, 4);
        vv *= (1.f / 128.f);
        if (ls == 0) { mu[j] = mm; rs[j] = rsqrtf(vv + 1e-5f); }
    }
    __syncthreads();

    #pragma unroll
    for (int it = 0; it < 16; it++) {
        int idx = tid + it * 256;
        int j = idx >> 7, d = idx & 127;
        float v = (xs[j][d] - mu[j]) * rs[j] * gam[d] + bet[d];
        xs[j][d] = v;
        int pos = pos0 + j;
        if (pos < QLEN) g_zln[(size_t)pos * 128 + d] = v;
    }
    __syncthreads();

    float acc[4][8];
    #pragma unroll
    for (int r = 0; r < 4; r++)
        #pragma unroll
        for (int c = 0; c < 8; c++) acc[r][c] = 0.f;

    const int j0 = (tid >> 5) * 4;
    const int i0 = (tid & 31) * 8;
    for (int d = 0; d < 128; d += 4) {
        float4 xv[4];
        #pragma unroll
        for (int r = 0; r < 4; r++) xv[r] = *(const float4*)&xs[j0 + r][d];
        #pragma unroll
        for (int c = 0; c < 8; c++) {
            float4 wv = __ldg((const float4*)&w1[(size_t)(i0 + c) * 128 + d]);
            #pragma unroll
            for (int r = 0; r < 4; r++)
                acc[r][c] += xv[r].x * wv.x + xv[r].y * wv.y + xv[r].z * wv.z + xv[r].w * wv.w;
        }
    }
    #pragma unroll
    for (int r = 0; r < 4; r++) {
        int pos = pos0 + j0 + r;
        if (pos < QLEN) {
            #pragma unroll
            for (int c = 0; c < 8; c++) {
                float u = acc[r][c] + b1[i0 + c];
                g_h1[(size_t)pos * 256 + i0 + c] =
                    0.5f * u * (1.f + erff(u * 0.70710678118654752f));
            }
        }
    }
}

// ============================================================================
// Kernel 6: fc2 (256->128) + residual + post-LN + transposed output [D][Q]
// ============================================================================
__global__ void __launch_bounds__(256)
mlp2(const float* __restrict__ w2, const float* __restrict__ b2,
     const float* __restrict__ gam, const float* __restrict__ bet,
     float* __restrict__ out)
{
    __shared__ float sbuf[32 * 264];
    __shared__ float mu[32], rs[32];
    const int tid = threadIdx.x;
    const int pos0 = blockIdx.x * 32;

    #pragma unroll
    for (int it = 0; it < 32; it++) {
        int idx = tid + it * 256;
        int j = idx >> 8, d = idx & 255;
        int pos = pos0 + j;
        sbuf[j * 264 + d] = (pos < QLEN) ? g_h1[(size_t)pos * 256 + d] : 0.f;
    }
    __syncthreads();

    float acc[4][4];
    #pragma unroll
    for (int r = 0; r < 4; r++)
        #pragma unroll
        for (int c = 0; c < 4; c++) acc[r][c] = 0.f;

    const int j0 = (tid >> 5) * 4;
    const int i0 = (tid & 31) * 4;
    for (int d = 0; d < 256; d += 4) {
        float4 xv[4];
        #pragma unroll
        for (int r = 0; r < 4; r++) xv[r] = *(const float4*)&sbuf[(j0 + r) * 264 + d];
        #pragma unroll
        for (int c = 0; c < 4; c++) {
            float4 wv = __ldg((const float4*)&w2[(size_t)(i0 + c) * 256 + d]);
            #pragma unroll
            for (int r = 0; r < 4; r++)
                acc[r][c] += xv[r].x * wv.x + xv[r].y * wv.y + xv[r].z * wv.z + xv[r].w * wv.w;
        }
    }
    __syncthreads();

    #pragma unroll
    for (int r = 0; r < 4; r++) {
        int pos = pos0 + j0 + r;
        #pragma unroll
        for (int c = 0; c < 4; c++) {
            float zl = (pos < QLEN) ? g_zln[(size_t)pos * 128 + i0 + c] : 0.f;
            sbuf[(j0 + r) * 132 + i0 + c] = acc[r][c] + b2[i0 + c] + zl;
        }
    }
    __syncthreads();

    {
        const int j = tid >> 3, ls = tid & 7;
        float mm = 0.f;
        #pragma unroll
        for (int d = ls; d < 128; d += 8) mm += sbuf[j * 132 + d];
        mm += __shfl_xor_sync(0xffffffffu, mm, 1);
        mm += __shfl_xor_sync(0xffffffffu, mm, 2);
        mm += __shfl_xor_sync(0xffffffffu, mm, 4);
        mm *= (1.f / 128.f);
        float vv = 0.f;
        #pragma unroll
        for (int d = ls; d < 128; d += 8) { float t = sbuf[j * 132 + d] - mm; vv += t * t; }
        vv += __shfl_xor_sync(0xffffffffu, vv, 1);
        vv += __shfl_xor_sync(0xffffffffu, vv, 2);
        vv += __shfl_xor_sync(0xffffffffu, vv, 4);
        vv *= (1.f / 128.f);
        if (ls == 0) { mu[j] = mm; rs[j] = rsqrtf(vv + 1e-5f); }
    }
    __syncthreads();

    #pragma unroll
    for (int it = 0; it < 16; it++) {
        int idx = tid + it * 256;
        int d = idx >> 5, j = idx & 31;
        int pos = pos0 + j;
        if (pos < QLEN)
            out[(size_t)d * QLEN + pos] =
                (sbuf[j * 132 + d] - mu[j]) * rs[j] * gam[d] + bet[d];
    }
}

// ============================================================================
// launch
// ============================================================================
extern "C" void kernel_launch(void* const* d_in, const int* in_sizes, int n_in,
                              void* d_out, int out_size)
{
    const float* q      = (const float*)d_in[0];
    const float* k      = (const float*)d_in[1];
    const float* v      = (const float*)d_in[2];
    const float* Wl     = (const float*)d_in[3];
    const int*   vis    = (const int*)  d_in[4];
    const float* skip   = (const float*)d_in[5];
    const float* qn_g   = (const float*)d_in[6];
    const float* qn_b   = (const float*)d_in[7];
    const float* kn_g   = (const float*)d_in[8];
    const float* kn_b   = (const float*)d_in[9];
    const float* vn_g   = (const float*)d_in[10];
    const float* vn_b   = (const float*)d_in[11];
    const float* wq     = (const float*)d_in[12];
    const float* bq     = (const float*)d_in[13];
    const float* wk     = (const float*)d_in[14];
    const float* bk     = (const float*)d_in[15];
    const float* wv     = (const float*)d_in[16];
    const float* bv     = (const float*)d_in[17];
    const float* wproj  = (const float*)d_in[18];
    const float* bproj  = (const float*)d_in[19];
    const float* pre_g  = (const float*)d_in[20];
    const float* pre_b  = (const float*)d_in[21];
    const float* w1     = (const float*)d_in[22];
    const float* b1     = (const float*)d_in[23];
    const float* w2     = (const float*)d_in[24];
    const float* b2     = (const float*)d_in[25];
    const float* post_g = (const float*)d_in[26];
    const float* post_b = (const float*)d_in[27];
    float* out = (float*)d_out;

    __nv_bfloat16 *qb_p, *kb_p, *vb_p;
    cudaGetSymbolAddress((void**)&qb_p, g_qbf);
    cudaGetSymbolAddress((void**)&kb_p, g_kbf);
    cudaGetSymbolAddress((void**)&vb_p, g_vbf);

    const int QB = (QLEN + 31) / 32;    // 79
    const int KB = (NKLEN + 31) / 32;   // 198

    ln_gemm_qkv<<<QB, 256>>>(q, QLEN, QLEN, qn_g, qn_b, wq, bq, qb_p);
    ln_gemm_qkv<<<KB, 256>>>(k, NKLEN, 1056, kn_g, kn_b, wk, bk, kb_p);
    ln_gemm_qkv<<<KB, 256>>>(v, NKLEN, 1056, vn_g, vn_b, wv, bv, vb_p);

    dim3 ag(QB, SPLITS);
    attn_kernel<<<ag, 256>>>(Wl, vis);

    combine_kernel<<<(NHEADS * QLEN + 127) / 128, 128>>>();

    proj_skip<<<QB, 256>>>(wproj, bproj, skip);
    mlp1<<<QB, 256>>>(pre_g, pre_b, w1, b1);
    mlp2<<<QB, 256>>>(w2, b2, post_g, post_b, out);
}

// round 5
// speedup vs baseline: 2.7955x; 1.4805x over previous
#include <cuda_runtime.h>
#include <cuda_bf16.h>
#include <cstdint>
#include <math.h>
#include <math_constants.h>

typedef unsigned int       u32;
typedef unsigned long long u64;

// ---------------- problem constants ----------------
#define QLEN   2500
#define NKLEN  6336
#define DMODEL 128
#define NHEADS 4
#define DHEAD  32
#define SPLITS 11
#define TPS    18           // 198 = 11 * 18 key tiles, exact
#define NKT    198
#define ATTN_SCALE 0.17677669529663688f
#define NEG_BIG (-3.402823466e38f)   // float32 finfo.min (reference semantics)

// attention pipeline smem layout (per stage)
#define KS_OFF   0
#define VS_OFF   10240
#define WS_OFF   20480
#define BV_OFF   25088
#define STAGEB   29696
#define NSTAGE   3

// ---------------- scratch ----------------
__device__ __nv_bfloat16 g_qbf[NHEADS * QLEN * DHEAD];
__device__ __nv_bfloat16 g_kbf[NHEADS * NKLEN * DHEAD];
__device__ __nv_bfloat16 g_vbf[NHEADS * NKLEN * DHEAD];
__device__ float g_pm[SPLITS * NHEADS * QLEN];
__device__ float g_ps[SPLITS * NHEADS * QLEN];
__device__ float g_pacc[SPLITS * NHEADS * QLEN * DHEAD];
__device__ float g_zln[QLEN * DMODEL];
__device__ float g_h1[QLEN * 2 * DMODEL];

// ---------------- helpers ----------------
__device__ __forceinline__ u32 packbf(float lo, float hi) {
    u32 r;
    asm("cvt.rn.bf16x2.f32 %0, %1, %2;" : "=r"(r) : "f"(hi), "f"(lo));
    return r;
}

__device__ __forceinline__ void mma16816(float (&c)[4],
                                         u32 a0, u32 a1, u32 a2, u32 a3,
                                         u32 b0, u32 b1) {
    asm volatile(
        "mma.sync.aligned.m16n8k16.row.col.f32.bf16.bf16.f32 "
        "{%0,%1,%2,%3}, {%4,%5,%6,%7}, {%8,%9}, {%0,%1,%2,%3};"
        : "+f"(c[0]), "+f"(c[1]), "+f"(c[2]), "+f"(c[3])
        : "r"(a0), "r"(a1), "r"(a2), "r"(a3), "r"(b0), "r"(b1));
}

__device__ __forceinline__ void cpa16(void* dst, const void* src) {
    u32 d = (u32)__cvta_generic_to_shared(dst);
    asm volatile("cp.async.cg.shared.global [%0], [%1], 16;" :: "r"(d), "l"(src));
}
__device__ __forceinline__ void cp_commit() { asm volatile("cp.async.commit_group;"); }
__device__ __forceinline__ void cp_wait1()  { asm volatile("cp.async.wait_group 1;"); }

// ============================================================================
// LN + 128x128 GEMM body -> bf16 planar [h][pos][32]
// input layout: x[(n*128 + d)*inner_pos + p], pos = n*inner_pos + p
// ============================================================================
__device__ __forceinline__ void ln_gemm_body(
    const float* __restrict__ x, int npos, int inner_pos,
    const float* __restrict__ gam, const float* __restrict__ bet,
    const float* __restrict__ w, const float* __restrict__ bw,
    __nv_bfloat16* __restrict__ outb, int pos0,
    float (*xs)[132], float* mu, float* rs)
{
    const int tid = threadIdx.x;

    #pragma unroll
    for (int it = 0; it < 16; it++) {
        int idx = tid + it * 256;
        int d = idx >> 5, j = idx & 31;
        int pos = pos0 + j;
        float v = 0.f;
        if (pos < npos) {
            int n = pos / inner_pos;
            int p = pos - n * inner_pos;
            v = x[((size_t)n * DMODEL + d) * (size_t)inner_pos + p];
        }
        xs[j][d] = v;
    }
    __syncthreads();

    {
        const int j = tid >> 3, ls = tid & 7;
        float mm = 0.f;
        #pragma unroll
        for (int d = ls; d < 128; d += 8) mm += xs[j][d];
        mm += __shfl_xor_sync(0xffffffffu, mm, 1);
        mm += __shfl_xor_sync(0xffffffffu, mm, 2);
        mm += __shfl_xor_sync(0xffffffffu, mm, 4);
        mm *= (1.f / 128.f);
        float vv = 0.f;
        #pragma unroll
        for (int d = ls; d < 128; d += 8) { float t = xs[j][d] - mm; vv += t * t; }
        vv += __shfl_xor_sync(0xffffffffu, vv, 1);
        vv += __shfl_xor_sync(0xffffffffu, vv, 2);
        vv += __shfl_xor_sync(0xffffffffu, vv, 4);
        vv *= (1.f / 128.f);
        if (ls == 0) { mu[j] = mm; rs[j] = rsqrtf(vv + 1e-5f); }
    }
    __syncthreads();

    #pragma unroll
    for (int it = 0; it < 16; it++) {
        int idx = tid + it * 256;
        int j = idx >> 7, d = idx & 127;
        xs[j][d] = (xs[j][d] - mu[j]) * rs[j] * gam[d] + bet[d];
    }
    __syncthreads();

    float acc[4][4];
    #pragma unroll
    for (int r = 0; r < 4; r++)
        #pragma unroll
        for (int c = 0; c < 4; c++) acc[r][c] = 0.f;

    const int j0 = (tid >> 5) * 4;
    const int i0 = (tid & 31) * 4;
    for (int d = 0; d < 128; d += 4) {
        float4 xv[4];
        #pragma unroll
        for (int r = 0; r < 4; r++) xv[r] = *(const float4*)&xs[j0 + r][d];
        #pragma unroll
        for (int c = 0; c < 4; c++) {
            float4 wv = __ldg((const float4*)&w[(size_t)(i0 + c) * 128 + d]);
            #pragma unroll
            for (int r = 0; r < 4; r++)
                acc[r][c] += xv[r].x * wv.x + xv[r].y * wv.y + xv[r].z * wv.z + xv[r].w * wv.w;
        }
    }
    const int h = i0 >> 5;
    const int dbase = i0 & 31;
    #pragma unroll
    for (int r = 0; r < 4; r++) {
        int pos = pos0 + j0 + r;
        if (pos < npos) {
            uint2 u;
            u.x = packbf(acc[r][0] + bw[i0 + 0], acc[r][1] + bw[i0 + 1]);
            u.y = packbf(acc[r][2] + bw[i0 + 2], acc[r][3] + bw[i0 + 3]);
            *(uint2*)&outb[((size_t)h * npos + pos) * DHEAD + dbase] = u;
        }
    }
}

// ============================================================================
// Kernel 1: fused QKV projections — one launch, 475 blocks
// ============================================================================
__global__ void __launch_bounds__(256)
qkv_fused(const float* __restrict__ q, const float* __restrict__ k, const float* __restrict__ v,
          const float* __restrict__ qn_g, const float* __restrict__ qn_b,
          const float* __restrict__ kn_g, const float* __restrict__ kn_b,
          const float* __restrict__ vn_g, const float* __restrict__ vn_b,
          const float* __restrict__ wq, const float* __restrict__ bq,
          const float* __restrict__ wk, const float* __restrict__ bk,
          const float* __restrict__ wv, const float* __restrict__ bv)
{
    __shared__ float xs[32][132];
    __shared__ float mu[32], rs[32];
    int b = blockIdx.x;
    if (b < 79) {
        ln_gemm_body(q, QLEN, QLEN, qn_g, qn_b, wq, bq, g_qbf, b * 32, xs, mu, rs);
    } else if (b < 277) {
        ln_gemm_body(k, NKLEN, 1056, kn_g, kn_b, wk, bk, g_kbf, (b - 79) * 32, xs, mu, rs);
    } else {
        ln_gemm_body(v, NKLEN, 1056, vn_g, vn_b, wv, bv, g_vbf, (b - 277) * 32, xs, mu, rs);
    }
}

// ============================================================================
// Kernel 2: HMMA bf16 flash attention, split-K, 3-stage cp.async pipeline.
// grid (79, 11). block 256 = 8 warps: (head = w&3, rowgrp = w>>2).
// ============================================================================
__device__ __forceinline__ void attn_issue_tile(char* stg, int qt, int k0,
                                                const float* __restrict__ Wl,
                                                const int* __restrict__ vis, int tid)
{
    // K/V: 4 heads x 32 keys x 64B rows; 512 x 16B chunks each
    #pragma unroll
    for (int c = tid; c < 512; c += 256) {
        int hh = c >> 7, key = (c >> 2) & 31, part = c & 3;
        size_t srcoff = ((size_t)(hh * NKLEN + k0 + key)) * DHEAD + part * 8;
        int doff = hh * 2560 + key * 80 + part * 16;
        cpa16(stg + KS_OFF + doff, g_kbf + srcoff);
        cpa16(stg + VS_OFF + doff, g_vbf + srcoff);
    }
    // W / vis: 32 rows x 128B; one 16B chunk per thread
    {
        int row = tid >> 3, part = tid & 7;
        int qq = qt * 32 + row; if (qq >= QLEN) qq = QLEN - 1;
        cpa16(stg + WS_OFF + row * 144 + part * 16, Wl  + (size_t)qq * NKLEN + k0 + part * 4);
        cpa16(stg + BV_OFF + row * 144 + part * 16, vis + (size_t)qq * NKLEN + k0 + part * 4);
    }
}

__global__ void __launch_bounds__(256, 2)
attn_kernel(const float* __restrict__ Wl, const int* __restrict__ vis)
{
    extern __shared__ char dsm[];

    const int tid = threadIdx.x;
    const int lane = tid & 31;
    const int wid = tid >> 5;
    const int h = wid & 3;
    const int rg = wid >> 2;
    const int g = lane >> 2;
    const int tx = lane & 3;
    const int qt = blockIdx.x;
    const int split = blockIdx.y;

    const int q0 = qt * 32 + rg * 16;
    const int r_lo = q0 + g;
    const int r_hi = q0 + g + 8;

    u32 aQ[2][4];
    #pragma unroll
    for (int kc = 0; kc < 2; kc++) {
        int c0 = kc * 16 + 2 * tx;
        aQ[kc][0] = (r_lo < QLEN) ? *(const u32*)&g_qbf[((size_t)h * QLEN + r_lo) * DHEAD + c0]     : 0u;
        aQ[kc][1] = (r_hi < QLEN) ? *(const u32*)&g_qbf[((size_t)h * QLEN + r_hi) * DHEAD + c0]     : 0u;
        aQ[kc][2] = (r_lo < QLEN) ? *(const u32*)&g_qbf[((size_t)h * QLEN + r_lo) * DHEAD + c0 + 8] : 0u;
        aQ[kc][3] = (r_hi < QLEN) ? *(const u32*)&g_qbf[((size_t)h * QLEN + r_hi) * DHEAD + c0 + 8] : 0u;
    }

    float acc[4][4];
    #pragma unroll
    for (int nc = 0; nc < 4; nc++)
        #pragma unroll
        for (int i = 0; i < 4; i++) acc[nc][i] = 0.f;
    float m0 = -CUDART_INF_F, m1 = -CUDART_INF_F, s0 = 0.f, s1 = 0.f;

    const int t0 = split * TPS;

    // prologue: prefetch stages 0 and 1
    attn_issue_tile(dsm + 0 * STAGEB, qt, (t0 + 0) * 32, Wl, vis, tid);
    cp_commit();
    attn_issue_tile(dsm + 1 * STAGEB, qt, (t0 + 1) * 32, Wl, vis, tid);
    cp_commit();

    for (int i = 0; i < TPS; i++) {
        cp_wait1();
        __syncthreads();
        char* stg = dsm + (i % NSTAGE) * STAGEB;

        // S = Q K^T
        float S[4][4];
        #pragma unroll
        for (int nc = 0; nc < 4; nc++) {
            S[nc][0] = 0.f; S[nc][1] = 0.f; S[nc][2] = 0.f; S[nc][3] = 0.f;
            #pragma unroll
            for (int kc = 0; kc < 2; kc++) {
                const char* kb = stg + KS_OFF + h * 2560 + (nc * 8 + g) * 80 + kc * 32 + tx * 4;
                u32 b0 = *(const u32*)kb;
                u32 b1 = *(const u32*)(kb + 16);
                mma16816(S[nc], aQ[kc][0], aQ[kc][1], aQ[kc][2], aQ[kc][3], b0, b1);
            }
        }

        // logits
        float l[4][4];
        const int wr_lo = rg * 16 + g;
        const int wr_hi = wr_lo + 8;
        #pragma unroll
        for (int nc = 0; nc < 4; nc++) {
            float2 wl = *(const float2*)(stg + WS_OFF + wr_lo * 144 + (nc * 8 + 2 * tx) * 4);
            float2 wh = *(const float2*)(stg + WS_OFF + wr_hi * 144 + (nc * 8 + 2 * tx) * 4);
            int2 bl = *(const int2*)(stg + BV_OFF + wr_lo * 144 + (nc * 8 + 2 * tx) * 4);
            int2 bh = *(const int2*)(stg + BV_OFF + wr_hi * 144 + (nc * 8 + 2 * tx) * 4);
            l[nc][0] = (bl.x == 0 ? NEG_BIG : S[nc][0] * ATTN_SCALE) * wl.x;
            l[nc][1] = (bl.y == 0 ? NEG_BIG : S[nc][1] * ATTN_SCALE) * wl.y;
            l[nc][2] = (bh.x == 0 ? NEG_BIG : S[nc][2] * ATTN_SCALE) * wh.x;
            l[nc][3] = (bh.y == 0 ? NEG_BIG : S[nc][3] * ATTN_SCALE) * wh.y;
        }

        // online softmax
        float mx0 = fmaxf(fmaxf(l[0][0], l[0][1]), fmaxf(l[1][0], l[1][1]));
        mx0 = fmaxf(mx0, fmaxf(fmaxf(l[2][0], l[2][1]), fmaxf(l[3][0], l[3][1])));
        float mx1 = fmaxf(fmaxf(l[0][2], l[0][3]), fmaxf(l[1][2], l[1][3]));
        mx1 = fmaxf(mx1, fmaxf(fmaxf(l[2][2], l[2][3]), fmaxf(l[3][2], l[3][3])));
        mx0 = fmaxf(mx0, __shfl_xor_sync(0xffffffffu, mx0, 1));
        mx0 = fmaxf(mx0, __shfl_xor_sync(0xffffffffu, mx0, 2));
        mx1 = fmaxf(mx1, __shfl_xor_sync(0xffffffffu, mx1, 1));
        mx1 = fmaxf(mx1, __shfl_xor_sync(0xffffffffu, mx1, 2));
        float mn0 = fmaxf(m0, mx0);
        float mn1 = fmaxf(m1, mx1);
        float cr0 = __expf(m0 - mn0);
        float cr1 = __expf(m1 - mn1);
        m0 = mn0; m1 = mn1;
        s0 *= cr0; s1 *= cr1;
        #pragma unroll
        for (int nc = 0; nc < 4; nc++) {
            acc[nc][0] *= cr0; acc[nc][1] *= cr0;
            acc[nc][2] *= cr1; acc[nc][3] *= cr1;
        }
        float p[4][4];
        #pragma unroll
        for (int nc = 0; nc < 4; nc++) {
            p[nc][0] = __expf(l[nc][0] - m0);
            p[nc][1] = __expf(l[nc][1] - m0);
            p[nc][2] = __expf(l[nc][2] - m1);
            p[nc][3] = __expf(l[nc][3] - m1);
            s0 += p[nc][0] + p[nc][1];
            s1 += p[nc][2] + p[nc][3];
        }

        // PV
        #pragma unroll
        for (int kc = 0; kc < 2; kc++) {
            u32 a0 = packbf(p[2 * kc][0],     p[2 * kc][1]);
            u32 a1 = packbf(p[2 * kc][2],     p[2 * kc][3]);
            u32 a2 = packbf(p[2 * kc + 1][0], p[2 * kc + 1][1]);
            u32 a3 = packbf(p[2 * kc + 1][2], p[2 * kc + 1][3]);
            int keyrow = kc * 16 + (lane & 15);
            #pragma unroll
            for (int nc = 0; nc < 4; nc++) {
                u32 addr = (u32)__cvta_generic_to_shared(
                    stg + VS_OFF + h * 2560 + keyrow * 80 + nc * 16);
                u32 b0, b1;
                asm volatile("ldmatrix.sync.aligned.m8n8.x2.trans.shared.b16 {%0,%1}, [%2];"
                             : "=r"(b0), "=r"(b1) : "r"(addr));
                mma16816(acc[nc], a0, a1, a2, a3, b0, b1);
            }
        }

        // prefetch stage i+2 (writes buffer (i+2)%3; safe: all threads synced above)
        if (i + 2 < TPS)
            attn_issue_tile(dsm + ((i + 2) % NSTAGE) * STAGEB, qt, (t0 + i + 2) * 32, Wl, vis, tid);
        cp_commit();
    }

    // epilogue
    s0 += __shfl_xor_sync(0xffffffffu, s0, 1);
    s0 += __shfl_xor_sync(0xffffffffu, s0, 2);
    s1 += __shfl_xor_sync(0xffffffffu, s1, 1);
    s1 += __shfl_xor_sync(0xffffffffu, s1, 2);

    const int base = (split * NHEADS + h) * QLEN;
    if (tx == 0) {
        if (r_lo < QLEN) { g_pm[base + r_lo] = m0; g_ps[base + r_lo] = s0; }
        if (r_hi < QLEN) { g_pm[base + r_hi] = m1; g_ps[base + r_hi] = s1; }
    }
    #pragma unroll
    for (int nc = 0; nc < 4; nc++) {
        if (r_lo < QLEN)
            *(float2*)&g_pacc[((size_t)(base + r_lo)) * DHEAD + nc * 8 + 2 * tx] =
                make_float2(acc[nc][0], acc[nc][1]);
        if (r_hi < QLEN)
            *(float2*)&g_pacc[((size_t)(base + r_hi)) * DHEAD + nc * 8 + 2 * tx] =
                make_float2(acc[nc][2], acc[nc][3]);
    }
}

// ============================================================================
// Kernel 3: fused epilogue — combine splits + out-proj + skip + pre-LN + fc1 + GELU
// ============================================================================
__global__ void __launch_bounds__(256)
epilogue_kernel(const float* __restrict__ wproj, const float* __restrict__ bproj,
                const float* __restrict__ skip,
                const float* __restrict__ pre_g, const float* __restrict__ pre_b,
                const float* __restrict__ w1, const float* __restrict__ b1)
{
    __shared__ float xs[32][132];
    __shared__ float zs[32][132];
    __shared__ float mu[32], rs[32];
    const int tid = threadIdx.x;
    const int pos0 = blockIdx.x * 32;

    // ---- combine split-K partials into xs[row][h*32+d] ----
    {
        int pair = tid >> 1;
        int row = pair >> 2, h = pair & 3;
        int dh0 = (tid & 1) * 16;
        int qrow = pos0 + row;
        if (qrow < QLEN) {
            float M = -CUDART_INF_F;
            #pragma unroll
            for (int s = 0; s < SPLITS; s++)
                M = fmaxf(M, g_pm[(s * NHEADS + h) * QLEN + qrow]);
            float S = 0.f;
            float a[16];
            #pragma unroll
            for (int d = 0; d < 16; d++) a[d] = 0.f;
            #pragma unroll
            for (int s = 0; s < SPLITS; s++) {
                int p = (s * NHEADS + h) * QLEN + qrow;
                float e = __expf(g_pm[p] - M);
                S += g_ps[p] * e;
                const float* pa = &g_pacc[(size_t)p * DHEAD + dh0];
                #pragma unroll
                for (int d = 0; d < 16; d++) a[d] += pa[d] * e;
            }
            float inv = 1.f / S;
            #pragma unroll
            for (int d = 0; d < 16; d++) xs[row][h * 32 + dh0 + d] = a[d] * inv;
        } else {
            #pragma unroll
            for (int d = 0; d < 16; d++) xs[row][h * 32 + dh0 + d] = 0.f;
        }
    }
    __syncthreads();

    // ---- out-proj GEMM + bias + skip -> zs ----
    {
        float acc[4][4];
        #pragma unroll
        for (int r = 0; r < 4; r++)
            #pragma unroll
            for (int c = 0; c < 4; c++) acc[r][c] = 0.f;

        const int j0 = (tid >> 5) * 4;
        const int i0 = (tid & 31) * 4;
        for (int d = 0; d < 128; d += 4) {
            float4 xv[4];
            #pragma unroll
            for (int r = 0; r < 4; r++) xv[r] = *(const float4*)&xs[j0 + r][d];
            #pragma unroll
            for (int c = 0; c < 4; c++) {
                float4 wv = __ldg((const float4*)&wproj[(size_t)(i0 + c) * 128 + d]);
                #pragma unroll
                for (int r = 0; r < 4; r++)
                    acc[r][c] += xv[r].x * wv.x + xv[r].y * wv.y + xv[r].z * wv.z + xv[r].w * wv.w;
            }
        }
        #pragma unroll
        for (int r = 0; r < 4; r++) {
            int pos = pos0 + j0 + r;
            #pragma unroll
            for (int c = 0; c < 4; c++) {
                zs[j0 + r][i0 + c] = (pos < QLEN)
                    ? acc[r][c] + bproj[i0 + c] + skip[(size_t)(i0 + c) * QLEN + pos]
                    : 0.f;
            }
        }
    }
    __syncthreads();

    // ---- pre-LN on zs; write g_zln; keep normalized in zs ----
    {
        const int j = tid >> 3, ls = tid & 7;
        float mm = 0.f;
        #pragma unroll
        for (int d = ls; d < 128; d += 8) mm += zs[j][d];
        mm += __shfl_xor_sync(0xffffffffu, mm, 1);
        mm += __shfl_xor_sync(0xffffffffu, mm, 2);
        mm += __shfl_xor_sync(0xffffffffu, mm, 4);
        mm *= (1.f / 128.f);
        float vv = 0.f;
        #pragma unroll
        for (int d = ls; d < 128; d += 8) { float t = zs[j][d] - mm; vv += t * t; }
        vv += __shfl_xor_sync(0xffffffffu, vv, 1);
        vv += __shfl_xor_sync(0xffffffffu, vv, 2);
        vv += __shfl_xor_sync(0xffffffffu, vv, 4);
        vv *= (1.f / 128.f);
        if (ls == 0) { mu[j] = mm; rs[j] = rsqrtf(vv + 1e-5f); }
    }
    __syncthreads();

    #pragma unroll
    for (int it = 0; it < 16; it++) {
        int idx = tid + it * 256;
        int j = idx >> 7, d = idx & 127;
        float v = (zs[j][d] - mu[j]) * rs[j] * pre_g[d] + pre_b[d];
        zs[j][d] = v;
        int pos = pos0 + j;
        if (pos < QLEN) g_zln[(size_t)pos * 128 + d] = v;
    }
    __syncthreads();

    // ---- fc1 (128->256) + exact GELU -> g_h1 ----
    {
        float acc[4][8];
        #pragma unroll
        for (int r = 0; r < 4; r++)
            #pragma unroll
            for (int c = 0; c < 8; c++) acc[r][c] = 0.f;

        const int j0 = (tid >> 5) * 4;
        const int i0 = (tid & 31) * 8;
        for (int d = 0; d < 128; d += 4) {
            float4 xv[4];
            #pragma unroll
            for (int r = 0; r < 4; r++) xv[r] = *(const float4*)&zs[j0 + r][d];
            #pragma unroll
            for (int c = 0; c < 8; c++) {
                float4 wv = __ldg((const float4*)&w1[(size_t)(i0 + c) * 128 + d]);
                #pragma unroll
                for (int r = 0; r < 4; r++)
                    acc[r][c] += xv[r].x * wv.x + xv[r].y * wv.y + xv[r].z * wv.z + xv[r].w * wv.w;
            }
        }
        #pragma unroll
        for (int r = 0; r < 4; r++) {
            int pos = pos0 + j0 + r;
            if (pos < QLEN) {
                #pragma unroll
                for (int c = 0; c < 8; c++) {
                    float u = acc[r][c] + b1[i0 + c];
                    g_h1[(size_t)pos * 256 + i0 + c] =
                        0.5f * u * (1.f + erff(u * 0.70710678118654752f));
                }
            }
        }
    }
}

// ============================================================================
// Kernel 4: fc2 (256->128) + residual + post-LN + transposed output [D][Q]
// ============================================================================
__global__ void __launch_bounds__(256)
mlp2(const float* __restrict__ w2, const float* __restrict__ b2,
     const float* __restrict__ gam, const float* __restrict__ bet,
     float* __restrict__ out)
{
    __shared__ float sbuf[32 * 264];
    __shared__ float mu[32], rs[32];
    const int tid = threadIdx.x;
    const int pos0 = blockIdx.x * 32;

    #pragma unroll
    for (int it = 0; it < 32; it++) {
        int idx = tid + it * 256;
        int j = idx >> 8, d = idx & 255;
        int pos = pos0 + j;
        sbuf[j * 264 + d] = (pos < QLEN) ? g_h1[(size_t)pos * 256 + d] : 0.f;
    }
    __syncthreads();

    float acc[4][4];
    #pragma unroll
    for (int r = 0; r < 4; r++)
        #pragma unroll
        for (int c = 0; c < 4; c++) acc[r][c] = 0.f;

    const int j0 = (tid >> 5) * 4;
    const int i0 = (tid & 31) * 4;
    for (int d = 0; d < 256; d += 4) {
        float4 xv[4];
        #pragma unroll
        for (int r = 0; r < 4; r++) xv[r] = *(const float4*)&sbuf[(j0 + r) * 264 + d];
        #pragma unroll
        for (int c = 0; c < 4; c++) {
            float4 wv = __ldg((const float4*)&w2[(size_t)(i0 + c) * 256 + d]);
            #pragma unroll
            for (int r = 0; r < 4; r++)
                acc[r][c] += xv[r].x * wv.x + xv[r].y * wv.y + xv[r].z * wv.z + xv[r].w * wv.w;
        }
    }
    __syncthreads();

    #pragma unroll
    for (int r = 0; r < 4; r++) {
        int pos = pos0 + j0 + r;
        #pragma unroll
        for (int c = 0; c < 4; c++) {
            float zl = (pos < QLEN) ? g_zln[(size_t)pos * 128 + i0 + c] : 0.f;
            sbuf[(j0 + r) * 132 + i0 + c] = acc[r][c] + b2[i0 + c] + zl;
        }
    }
    __syncthreads();

    {
        const int j = tid >> 3, ls = tid & 7;
        float mm = 0.f;
        #pragma unroll
        for (int d = ls; d < 128; d += 8) mm += sbuf[j * 132 + d];
        mm += __shfl_xor_sync(0xffffffffu, mm, 1);
        mm += __shfl_xor_sync(0xffffffffu, mm, 2);
        mm += __shfl_xor_sync(0xffffffffu, mm, 4);
        mm *= (1.f / 128.f);
        float vv = 0.f;
        #pragma unroll
        for (int d = ls; d < 128; d += 8) { float t = sbuf[j * 132 + d] - mm; vv += t * t; }
        vv += __shfl_xor_sync(0xffffffffu, vv, 1);
        vv += __shfl_xor_sync(0xffffffffu, vv, 2);
        vv += __shfl_xor_sync(0xffffffffu, vv, 4);
        vv *= (1.f / 128.f);
        if (ls == 0) { mu[j] = mm; rs[j] = rsqrtf(vv + 1e-5f); }
    }
    __syncthreads();

    #pragma unroll
    for (int it = 0; it < 16; it++) {
        int idx = tid + it * 256;
        int d = idx >> 5, j = idx & 31;
        int pos = pos0 + j;
        if (pos < QLEN)
            out[(size_t)d * QLEN + pos] =
                (sbuf[j * 132 + d] - mu[j]) * rs[j] * gam[d] + bet[d];
    }
}

// ============================================================================
// launch
// ============================================================================
extern "C" void kernel_launch(void* const* d_in, const int* in_sizes, int n_in,
                              void* d_out, int out_size)
{
    const float* q      = (const float*)d_in[0];
    const float* k      = (const float*)d_in[1];
    const float* v      = (const float*)d_in[2];
    const float* Wl     = (const float*)d_in[3];
    const int*   vis    = (const int*)  d_in[4];
    const float* skip   = (const float*)d_in[5];
    const float* qn_g   = (const float*)d_in[6];
    const float* qn_b   = (const float*)d_in[7];
    const float* kn_g   = (const float*)d_in[8];
    const float* kn_b   = (const float*)d_in[9];
    const float* vn_g   = (const float*)d_in[10];
    const float* vn_b   = (const float*)d_in[11];
    const float* wq     = (const float*)d_in[12];
    const float* bq     = (const float*)d_in[13];
    const float* wk     = (const float*)d_in[14];
    const float* bk     = (const float*)d_in[15];
    const float* wv     = (const float*)d_in[16];
    const float* bv     = (const float*)d_in[17];
    const float* wproj  = (const float*)d_in[18];
    const float* bproj  = (const float*)d_in[19];
    const float* pre_g  = (const float*)d_in[20];
    const float* pre_b  = (const float*)d_in[21];
    const float* w1     = (const float*)d_in[22];
    const float* b1     = (const float*)d_in[23];
    const float* w2     = (const float*)d_in[24];
    const float* b2     = (const float*)d_in[25];
    const float* post_g = (const float*)d_in[26];
    const float* post_b = (const float*)d_in[27];
    float* out = (float*)d_out;

    const int ATTN_SMEM = NSTAGE * STAGEB;   // 89088
    cudaFuncSetAttribute(attn_kernel, cudaFuncAttributeMaxDynamicSharedMemorySize, ATTN_SMEM);

    const int QB = (QLEN + 31) / 32;    // 79

    qkv_fused<<<475, 256>>>(q, k, v, qn_g, qn_b, kn_g, kn_b, vn_g, vn_b,
                            wq, bq, wk, bk, wv, bv);

    dim3 ag(QB, SPLITS);
    attn_kernel<<<ag, 256, ATTN_SMEM>>>(Wl, vis);

    epilogue_kernel<<<QB, 256>>>(wproj, bproj, skip, pre_g, pre_b, w1, b1);

    mlp2<<<QB, 256>>>(w2, b2, post_g, post_b, out);
}